// round 2
// baseline (speedup 1.0000x reference)
#include <cuda_runtime.h>
#include <cstdint>

// Scratch: per-node projection (pu0, pu1, pv0, pv1). 50000 * 16B = 800 KB.
// Sized generously in case of shape variants.
#define MAX_NODES 131072
__device__ float4 g_node_proj[MAX_NODES];

#define D_DIM 128
#define E_DIM 64

// Kernel 1: proj[n] = (nf[n]@Wu, nf[n]@Wv). One warp per node.
__global__ void node_proj_kernel(const float* __restrict__ nf,
                                 const float* __restrict__ W,  // [2D+E_DIM, 2]
                                 int n_nodes) {
    __shared__ float2 sW[2 * D_DIM];  // sW[k] = (W[k][0], W[k][1]), k in [0, 256)
    for (int i = threadIdx.x; i < 2 * D_DIM; i += blockDim.x)
        sW[i] = make_float2(W[2 * i], W[2 * i + 1]);
    __syncthreads();

    int warp = (blockIdx.x * blockDim.x + threadIdx.x) >> 5;
    int lane = threadIdx.x & 31;
    if (warp >= n_nodes) return;

    const float4* row = reinterpret_cast<const float4*>(nf + (size_t)warp * D_DIM);
    float4 v = row[lane];  // 32 lanes * 4 = 128 dims
    int k = lane * 4;

    float pu0 = 0.f, pu1 = 0.f, pv0 = 0.f, pv1 = 0.f;
    float vals[4] = {v.x, v.y, v.z, v.w};
#pragma unroll
    for (int j = 0; j < 4; j++) {
        float2 wu = sW[k + j];
        float2 wv = sW[D_DIM + k + j];
        pu0 = fmaf(vals[j], wu.x, pu0);
        pu1 = fmaf(vals[j], wu.y, pu1);
        pv0 = fmaf(vals[j], wv.x, pv0);
        pv1 = fmaf(vals[j], wv.y, pv1);
    }
#pragma unroll
    for (int off = 16; off; off >>= 1) {
        pu0 += __shfl_xor_sync(0xffffffffu, pu0, off);
        pu1 += __shfl_xor_sync(0xffffffffu, pu1, off);
        pv0 += __shfl_xor_sync(0xffffffffu, pv0, off);
        pv1 += __shfl_xor_sync(0xffffffffu, pv1, off);
    }
    if (lane == 0) g_node_proj[warp] = make_float4(pu0, pu1, pv0, pv1);
}

// Kernel 2: out[e] = proj[src[e]].(x,y) + proj[dst[e]].(z,w) + ef[e]@We + b.
// 16 threads per edge; each lane loads one float4 (coalesced 256B per edge).
__global__ void edge_score_kernel(const float* __restrict__ ef,
                                  const int* __restrict__ src,
                                  const int* __restrict__ dst,
                                  const float* __restrict__ W,  // [2D+E_DIM, 2]
                                  const float* __restrict__ b,  // [2]
                                  float2* __restrict__ out,
                                  int n_edges) {
    __shared__ float2 sWe[E_DIM];
    __shared__ float2 sb;
    if (threadIdx.x < E_DIM) {
        int k = 2 * D_DIM + threadIdx.x;
        sWe[threadIdx.x] = make_float2(W[2 * k], W[2 * k + 1]);
    }
    if (threadIdx.x == 0) sb = make_float2(b[0], b[1]);
    __syncthreads();

    int gid = blockIdx.x * blockDim.x + threadIdx.x;
    int edge = gid >> 4;
    int lane16 = gid & 15;
    if (edge >= n_edges) return;

    const float4* row = reinterpret_cast<const float4*>(ef + (size_t)edge * E_DIM);
    float4 v = row[lane16];
    int k = lane16 * 4;

    float2 w0 = sWe[k], w1 = sWe[k + 1], w2 = sWe[k + 2], w3 = sWe[k + 3];
    float s0 = v.x * w0.x + v.y * w1.x + v.z * w2.x + v.w * w3.x;
    float s1 = v.x * w0.y + v.y * w1.y + v.z * w2.y + v.w * w3.y;

    // Reduce within the 16-lane group (offsets < 16 stay within each half-warp).
#pragma unroll
    for (int off = 8; off; off >>= 1) {
        s0 += __shfl_xor_sync(0xffffffffu, s0, off);
        s1 += __shfl_xor_sync(0xffffffffu, s1, off);
    }

    if (lane16 == 0) {
        float4 pu = g_node_proj[src[edge]];
        float4 pv = g_node_proj[dst[edge]];
        out[edge] = make_float2(s0 + pu.x + pv.z + sb.x,
                                s1 + pu.y + pv.w + sb.y);
    }
}

extern "C" void kernel_launch(void* const* d_in, const int* in_sizes, int n_in,
                              void* d_out, int out_size) {
    // metadata order: node_feats [N,128], edge_feats [E,64], src [E] i32,
    //                 dst [E] i32, W [320,2], b [2]
    const float* node_feats = (const float*)d_in[0];
    const float* edge_feats = (const float*)d_in[1];
    const int*   src        = (const int*)d_in[2];
    const int*   dst        = (const int*)d_in[3];
    const float* W          = (const float*)d_in[4];
    const float* b          = (const float*)d_in[5];
    float2* out = (float2*)d_out;

    int n_nodes = in_sizes[0] / D_DIM;
    int n_edges = in_sizes[2];

    // Kernel 1: one warp per node, 8 warps per block.
    {
        int threads = 256;
        int warps_per_block = threads / 32;
        int blocks = (n_nodes + warps_per_block - 1) / warps_per_block;
        node_proj_kernel<<<blocks, threads>>>(node_feats, W, n_nodes);
    }

    // Kernel 2: 16 threads per edge, 16 edges per 256-thread block.
    {
        int threads = 256;
        int edges_per_block = threads / 16;
        int blocks = (n_edges + edges_per_block - 1) / edges_per_block;
        edge_score_kernel<<<blocks, threads>>>(edge_feats, src, dst, W, b,
                                               out, n_edges);
    }
}

// round 3
// speedup vs baseline: 1.5727x; 1.5727x over previous
#include <cuda_runtime.h>
#include <cstdint>

// Scratch: per-node projection (pu0, pu1, pv0, pv1). 50000 * 16B = 800 KB.
#define MAX_NODES 131072
__device__ float4 g_node_proj[MAX_NODES];

#define D_DIM 128
#define E_DIM 64

// Kernel 1: proj[n] = (nf[n]@Wu, nf[n]@Wv). One warp per node.
__global__ void node_proj_kernel(const float* __restrict__ nf,
                                 const float* __restrict__ W,  // [2D+E_DIM, 2]
                                 int n_nodes) {
    __shared__ float2 sW[2 * D_DIM];  // sW[k] = (W[k][0], W[k][1])
    for (int i = threadIdx.x; i < 2 * D_DIM; i += blockDim.x)
        sW[i] = make_float2(W[2 * i], W[2 * i + 1]);
    __syncthreads();

    int warp = (blockIdx.x * blockDim.x + threadIdx.x) >> 5;
    int lane = threadIdx.x & 31;
    if (warp >= n_nodes) return;

    const float4* row = reinterpret_cast<const float4*>(nf + (size_t)warp * D_DIM);
    float4 v = row[lane];
    int k = lane * 4;

    float pu0 = 0.f, pu1 = 0.f, pv0 = 0.f, pv1 = 0.f;
    float vals[4] = {v.x, v.y, v.z, v.w};
#pragma unroll
    for (int j = 0; j < 4; j++) {
        float2 wu = sW[k + j];
        float2 wv = sW[D_DIM + k + j];
        pu0 = fmaf(vals[j], wu.x, pu0);
        pu1 = fmaf(vals[j], wu.y, pu1);
        pv0 = fmaf(vals[j], wv.x, pv0);
        pv1 = fmaf(vals[j], wv.y, pv1);
    }
#pragma unroll
    for (int off = 16; off; off >>= 1) {
        pu0 += __shfl_xor_sync(0xffffffffu, pu0, off);
        pu1 += __shfl_xor_sync(0xffffffffu, pu1, off);
        pv0 += __shfl_xor_sync(0xffffffffu, pv0, off);
        pv1 += __shfl_xor_sync(0xffffffffu, pv1, off);
    }
    if (lane == 0) g_node_proj[warp] = make_float4(pu0, pu1, pv0, pv1);
}

// Kernel 2: 4 lanes per edge, We register-resident, grid-stride.
// out[e] = proj[src[e]].(x,y) + proj[dst[e]].(z,w) + ef[e]@We + b
__global__ void edge_score_kernel(const float* __restrict__ ef,
                                  const int* __restrict__ src,
                                  const int* __restrict__ dst,
                                  const float* __restrict__ W,  // [2D+E_DIM, 2]
                                  const float* __restrict__ b,  // [2]
                                  float2* __restrict__ out,
                                  int n_edges) {
    const int lane4 = threadIdx.x & 3;

    // Register-cache this lane's 16 weight pairs:
    //   float4 index f = lane4 + 4*i  ->  k = 4*f + j
    float2 w[16];
#pragma unroll
    for (int i = 0; i < 4; i++) {
#pragma unroll
        for (int j = 0; j < 4; j++) {
            int k = 2 * D_DIM + 4 * (lane4 + 4 * i) + j;
            w[i * 4 + j] = *reinterpret_cast<const float2*>(W + 2 * k);
        }
    }
    const float b0 = b[0], b1 = b[1];

    int group = (blockIdx.x * blockDim.x + threadIdx.x) >> 2;
    int n_groups = (gridDim.x * blockDim.x) >> 2;

    for (int e = group; e < n_edges; e += n_groups) {
        const float4* row = reinterpret_cast<const float4*>(ef) + (size_t)e * 16;

        // 4 independent 16B loads per thread (MLP=4), coalesced 64B per edge.
        float4 v0 = row[lane4];
        float4 v1 = row[lane4 + 4];
        float4 v2 = row[lane4 + 8];
        float4 v3 = row[lane4 + 12];

        // Index + proj gathers (duplicated across the 4 lanes -> sector-merged).
        int si = src[e];
        int di = dst[e];
        float4 pu = g_node_proj[si];
        float4 pv = g_node_proj[di];

        float s0, s1;
        s0 = v0.x * w[0].x;                 s1 = v0.x * w[0].y;
        s0 = fmaf(v0.y, w[1].x, s0);        s1 = fmaf(v0.y, w[1].y, s1);
        s0 = fmaf(v0.z, w[2].x, s0);        s1 = fmaf(v0.z, w[2].y, s1);
        s0 = fmaf(v0.w, w[3].x, s0);        s1 = fmaf(v0.w, w[3].y, s1);
        s0 = fmaf(v1.x, w[4].x, s0);        s1 = fmaf(v1.x, w[4].y, s1);
        s0 = fmaf(v1.y, w[5].x, s0);        s1 = fmaf(v1.y, w[5].y, s1);
        s0 = fmaf(v1.z, w[6].x, s0);        s1 = fmaf(v1.z, w[6].y, s1);
        s0 = fmaf(v1.w, w[7].x, s0);        s1 = fmaf(v1.w, w[7].y, s1);
        s0 = fmaf(v2.x, w[8].x, s0);        s1 = fmaf(v2.x, w[8].y, s1);
        s0 = fmaf(v2.y, w[9].x, s0);        s1 = fmaf(v2.y, w[9].y, s1);
        s0 = fmaf(v2.z, w[10].x, s0);       s1 = fmaf(v2.z, w[10].y, s1);
        s0 = fmaf(v2.w, w[11].x, s0);       s1 = fmaf(v2.w, w[11].y, s1);
        s0 = fmaf(v3.x, w[12].x, s0);       s1 = fmaf(v3.x, w[12].y, s1);
        s0 = fmaf(v3.y, w[13].x, s0);       s1 = fmaf(v3.y, w[13].y, s1);
        s0 = fmaf(v3.z, w[14].x, s0);       s1 = fmaf(v3.z, w[14].y, s1);
        s0 = fmaf(v3.w, w[15].x, s0);       s1 = fmaf(v3.w, w[15].y, s1);

        // Reduce across the 4 lanes of this edge (2 butterfly levels).
        s0 += __shfl_xor_sync(0xffffffffu, s0, 1);
        s1 += __shfl_xor_sync(0xffffffffu, s1, 1);
        s0 += __shfl_xor_sync(0xffffffffu, s0, 2);
        s1 += __shfl_xor_sync(0xffffffffu, s1, 2);

        if (lane4 == 0) {
            out[e] = make_float2(s0 + pu.x + pv.z + b0,
                                 s1 + pu.y + pv.w + b1);
        }
    }
}

extern "C" void kernel_launch(void* const* d_in, const int* in_sizes, int n_in,
                              void* d_out, int out_size) {
    const float* node_feats = (const float*)d_in[0];
    const float* edge_feats = (const float*)d_in[1];
    const int*   src        = (const int*)d_in[2];
    const int*   dst        = (const int*)d_in[3];
    const float* W          = (const float*)d_in[4];
    const float* b          = (const float*)d_in[5];
    float2* out = (float2*)d_out;

    int n_nodes = in_sizes[0] / D_DIM;
    int n_edges = in_sizes[2];

    // Kernel 1: one warp per node.
    {
        int threads = 256;
        int warps_per_block = threads / 32;
        int blocks = (n_nodes + warps_per_block - 1) / warps_per_block;
        node_proj_kernel<<<blocks, threads>>>(node_feats, W, n_nodes);
    }

    // Kernel 2: 4 lanes per edge, grid-stride.
    {
        int threads = 256;
        int groups_per_block = threads / 4;  // 64 edges per block-iteration
        int blocks = 1480;                   // ~10 per SM; grid-stride covers E
        int max_blocks = (n_edges + groups_per_block - 1) / groups_per_block;
        if (blocks > max_blocks) blocks = max_blocks;
        edge_score_kernel<<<blocks, threads>>>(edge_feats, src, dst, W, b,
                                               out, n_edges);
    }
}

// round 4
// speedup vs baseline: 1.8257x; 1.1609x over previous
#include <cuda_runtime.h>
#include <cstdint>

// Scratch: per-node projection (pu0, pu1, pv0, pv1). 50000 * 16B = 800 KB.
#define MAX_NODES 131072
__device__ float4 g_node_proj[MAX_NODES];

#define D_DIM 128
#define E_DIM 64

// Kernel 1: proj[n] = (nf[n]@Wu, nf[n]@Wv). 16 lanes per node, register weights.
__global__ void node_proj_kernel(const float* __restrict__ nf,
                                 const float* __restrict__ W,  // [2D+E_DIM, 2]
                                 int n_nodes) {
    int gid = blockIdx.x * blockDim.x + threadIdx.x;
    int node = gid >> 4;
    int lane16 = gid & 15;
    bool valid = (node < n_nodes);

    const float2* W2 = reinterpret_cast<const float2*>(W);  // W2[k] = (W[k][0], W[k][1])

    // This lane covers dims [4*lane16, 4*lane16+4) and [64+4*lane16, 64+4*lane16+4).
    // Weight pairs for those dims, Wu (k base 0) and Wv (k base 128), as float4s.
    float4 wu_lo0 = *reinterpret_cast<const float4*>(&W2[4 * lane16]);
    float4 wu_lo1 = *reinterpret_cast<const float4*>(&W2[4 * lane16 + 2]);
    float4 wu_hi0 = *reinterpret_cast<const float4*>(&W2[64 + 4 * lane16]);
    float4 wu_hi1 = *reinterpret_cast<const float4*>(&W2[64 + 4 * lane16 + 2]);
    float4 wv_lo0 = *reinterpret_cast<const float4*>(&W2[128 + 4 * lane16]);
    float4 wv_lo1 = *reinterpret_cast<const float4*>(&W2[128 + 4 * lane16 + 2]);
    float4 wv_hi0 = *reinterpret_cast<const float4*>(&W2[192 + 4 * lane16]);
    float4 wv_hi1 = *reinterpret_cast<const float4*>(&W2[192 + 4 * lane16 + 2]);

    float4 a = make_float4(0.f, 0.f, 0.f, 0.f);
    float4 c = make_float4(0.f, 0.f, 0.f, 0.f);
    if (valid) {
        const float4* row = reinterpret_cast<const float4*>(nf + (size_t)node * D_DIM);
        a = row[lane16];       // dims 4*lane16 ..
        c = row[lane16 + 16];  // dims 64 + 4*lane16 ..
    }

    float pu0, pu1, pv0, pv1;
    pu0 = a.x * wu_lo0.x;            pu1 = a.x * wu_lo0.y;
    pv0 = a.x * wv_lo0.x;            pv1 = a.x * wv_lo0.y;
    pu0 = fmaf(a.y, wu_lo0.z, pu0);  pu1 = fmaf(a.y, wu_lo0.w, pu1);
    pv0 = fmaf(a.y, wv_lo0.z, pv0);  pv1 = fmaf(a.y, wv_lo0.w, pv1);
    pu0 = fmaf(a.z, wu_lo1.x, pu0);  pu1 = fmaf(a.z, wu_lo1.y, pu1);
    pv0 = fmaf(a.z, wv_lo1.x, pv0);  pv1 = fmaf(a.z, wv_lo1.y, pv1);
    pu0 = fmaf(a.w, wu_lo1.z, pu0);  pu1 = fmaf(a.w, wu_lo1.w, pu1);
    pv0 = fmaf(a.w, wv_lo1.z, pv0);  pv1 = fmaf(a.w, wv_lo1.w, pv1);
    pu0 = fmaf(c.x, wu_hi0.x, pu0);  pu1 = fmaf(c.x, wu_hi0.y, pu1);
    pv0 = fmaf(c.x, wv_hi0.x, pv0);  pv1 = fmaf(c.x, wv_hi0.y, pv1);
    pu0 = fmaf(c.y, wu_hi0.z, pu0);  pu1 = fmaf(c.y, wu_hi0.w, pu1);
    pv0 = fmaf(c.y, wv_hi0.z, pv0);  pv1 = fmaf(c.y, wv_hi0.w, pv1);
    pu0 = fmaf(c.z, wu_hi1.x, pu0);  pu1 = fmaf(c.z, wu_hi1.y, pu1);
    pv0 = fmaf(c.z, wv_hi1.x, pv0);  pv1 = fmaf(c.z, wv_hi1.y, pv1);
    pu0 = fmaf(c.w, wu_hi1.z, pu0);  pu1 = fmaf(c.w, wu_hi1.w, pu1);
    pv0 = fmaf(c.w, wv_hi1.z, pv0);  pv1 = fmaf(c.w, wv_hi1.w, pv1);

#pragma unroll
    for (int off = 8; off; off >>= 1) {
        pu0 += __shfl_xor_sync(0xffffffffu, pu0, off);
        pu1 += __shfl_xor_sync(0xffffffffu, pu1, off);
        pv0 += __shfl_xor_sync(0xffffffffu, pv0, off);
        pv1 += __shfl_xor_sync(0xffffffffu, pv1, off);
    }
    if (valid && lane16 == 0) g_node_proj[node] = make_float4(pu0, pu1, pv0, pv1);
}

// Kernel 2: 4 lanes per edge, register weights, software-pipelined grid-stride.
// out[e] = proj[src[e]].(x,y) + proj[dst[e]].(z,w) + ef[e]@We + b
__global__ void edge_score_kernel(const float* __restrict__ ef,
                                  const int* __restrict__ src,
                                  const int* __restrict__ dst,
                                  const float* __restrict__ W,
                                  const float* __restrict__ b,
                                  float2* __restrict__ out,
                                  int n_edges) {
    const int lane4 = threadIdx.x & 3;
    const float2* W2 = reinterpret_cast<const float2*>(W);

    // 16 weight pairs for this lane: float4 index f = lane4 + 4*i, k = 2D + 4f + j.
    float2 w[16];
#pragma unroll
    for (int i = 0; i < 4; i++) {
        int kb = 2 * D_DIM + 4 * (lane4 + 4 * i);
        float4 p0 = *reinterpret_cast<const float4*>(&W2[kb]);
        float4 p1 = *reinterpret_cast<const float4*>(&W2[kb + 2]);
        w[4 * i + 0] = make_float2(p0.x, p0.y);
        w[4 * i + 1] = make_float2(p0.z, p0.w);
        w[4 * i + 2] = make_float2(p1.x, p1.y);
        w[4 * i + 3] = make_float2(p1.z, p1.w);
    }
    const float b0 = b[0], b1 = b[1];

    const int group = (blockIdx.x * blockDim.x + threadIdx.x) >> 2;
    const int n_groups = (gridDim.x * blockDim.x) >> 2;
    // Warp-uniform loop bound: first group of this warp.
    const int warp_g0 = group & ~7;

    int e = group;
    int we = warp_g0;  // warp-uniform cursor

    // Prologue: load first edge (predicated).
    float4 v0, v1, v2, v3;
    int si = 0, di = 0;
    v0 = v1 = v2 = v3 = make_float4(0.f, 0.f, 0.f, 0.f);
    if (e < n_edges) {
        const float4* row = reinterpret_cast<const float4*>(ef) + (size_t)e * 16;
        v0 = row[lane4];
        v1 = row[lane4 + 4];
        v2 = row[lane4 + 8];
        v3 = row[lane4 + 12];
        si = src[e];
        di = dst[e];
    }

    while (we < n_edges) {
        int en = e + n_groups;
        // Prefetch next iteration (predicated; overlaps with compute below).
        float4 m0, m1, m2, m3;
        int sn = 0, dn = 0;
        m0 = m1 = m2 = m3 = make_float4(0.f, 0.f, 0.f, 0.f);
        if (en < n_edges) {
            const float4* rn = reinterpret_cast<const float4*>(ef) + (size_t)en * 16;
            m0 = rn[lane4];
            m1 = rn[lane4 + 4];
            m2 = rn[lane4 + 8];
            m3 = rn[lane4 + 12];
            sn = src[en];
            dn = dst[en];
        }

        // proj gathers for the current edge (L2-resident; hidden under the FMAs).
        float4 pu = g_node_proj[si];
        float4 pv = g_node_proj[di];

        // 4 accumulators -> dependency chain of 8 FMAs.
        float s0a, s1a, s0b, s1b;
        s0a = v0.x * w[0].x;             s1a = v0.x * w[0].y;
        s0b = v2.x * w[8].x;             s1b = v2.x * w[8].y;
        s0a = fmaf(v0.y, w[1].x, s0a);   s1a = fmaf(v0.y, w[1].y, s1a);
        s0b = fmaf(v2.y, w[9].x, s0b);   s1b = fmaf(v2.y, w[9].y, s1b);
        s0a = fmaf(v0.z, w[2].x, s0a);   s1a = fmaf(v0.z, w[2].y, s1a);
        s0b = fmaf(v2.z, w[10].x, s0b);  s1b = fmaf(v2.z, w[10].y, s1b);
        s0a = fmaf(v0.w, w[3].x, s0a);   s1a = fmaf(v0.w, w[3].y, s1a);
        s0b = fmaf(v2.w, w[11].x, s0b);  s1b = fmaf(v2.w, w[11].y, s1b);
        s0a = fmaf(v1.x, w[4].x, s0a);   s1a = fmaf(v1.x, w[4].y, s1a);
        s0b = fmaf(v3.x, w[12].x, s0b);  s1b = fmaf(v3.x, w[12].y, s1b);
        s0a = fmaf(v1.y, w[5].x, s0a);   s1a = fmaf(v1.y, w[5].y, s1a);
        s0b = fmaf(v3.y, w[13].x, s0b);  s1b = fmaf(v3.y, w[13].y, s1b);
        s0a = fmaf(v1.z, w[6].x, s0a);   s1a = fmaf(v1.z, w[6].y, s1a);
        s0b = fmaf(v3.z, w[14].x, s0b);  s1b = fmaf(v3.z, w[14].y, s1b);
        s0a = fmaf(v1.w, w[7].x, s0a);   s1a = fmaf(v1.w, w[7].y, s1a);
        s0b = fmaf(v3.w, w[15].x, s0b);  s1b = fmaf(v3.w, w[15].y, s1b);

        float s0 = s0a + s0b;
        float s1 = s1a + s1b;

        // Reduce across the 4 lanes (all 32 lanes execute: uniform trip count).
        s0 += __shfl_xor_sync(0xffffffffu, s0, 1);
        s1 += __shfl_xor_sync(0xffffffffu, s1, 1);
        s0 += __shfl_xor_sync(0xffffffffu, s0, 2);
        s1 += __shfl_xor_sync(0xffffffffu, s1, 2);

        if (lane4 == 0 && e < n_edges) {
            out[e] = make_float2(s0 + pu.x + pv.z + b0,
                                 s1 + pu.y + pv.w + b1);
        }

        // Rotate pipeline.
        e = en;
        we += n_groups;
        v0 = m0; v1 = m1; v2 = m2; v3 = m3;
        si = sn; di = dn;
    }
}

extern "C" void kernel_launch(void* const* d_in, const int* in_sizes, int n_in,
                              void* d_out, int out_size) {
    const float* node_feats = (const float*)d_in[0];
    const float* edge_feats = (const float*)d_in[1];
    const int*   src        = (const int*)d_in[2];
    const int*   dst        = (const int*)d_in[3];
    const float* W          = (const float*)d_in[4];
    const float* b          = (const float*)d_in[5];
    float2* out = (float2*)d_out;

    int n_nodes = in_sizes[0] / D_DIM;
    int n_edges = in_sizes[2];

    // Kernel 1: 16 lanes per node, 16 nodes per 256-thread block.
    {
        int threads = 256;
        int nodes_per_block = threads / 16;
        int blocks = (n_nodes + nodes_per_block - 1) / nodes_per_block;
        node_proj_kernel<<<blocks, threads>>>(node_feats, W, n_nodes);
    }

    // Kernel 2: 4 lanes per edge, software-pipelined grid-stride.
    {
        int threads = 256;
        int groups_per_block = threads / 4;
        int blocks = 1480;
        int max_blocks = (n_edges + groups_per_block - 1) / groups_per_block;
        if (blocks > max_blocks) blocks = max_blocks;
        edge_score_kernel<<<blocks, threads>>>(edge_feats, src, dst, W, b,
                                               out, n_edges);
    }
}